// round 13
// baseline (speedup 1.0000x reference)
#include <cuda_runtime.h>
#include <cstdint>

// Net_60413009985719 — R13: instrumentation round, take 3 (previous two
// attempts died to broker-side container failures; this build differs from
// the failed one: REPS=4). R9 pipeline wrapped in an outer rep loop, every
// iteration recomputing the full result identically and deterministically.
// body_per_rep = (dur(4) - 10.62us) / 3.  Discriminates in-kernel cycles
// vs per-replay launch overhead.

#define H 64
#define ROWS 192
#define WPAD 68
#define NT 512
#define REPS 4

#define OFF_W    0
#define OFF_FC   (OFF_W + 4*ROWS*WPAD)
#define OFF_W0   (OFF_FC + 32*WPAD)
#define OFF_B0   (OFF_W0 + ROWS)
#define OFF_BS   (OFF_B0 + ROWS)
#define OFF_C1W  (OFF_BS + 4*ROWS)
#define OFF_C1B  (OFF_C1W + 512)
#define OFF_FCB  (OFF_C1B + 16)
#define OFF_MW   (OFF_FCB + 32)
#define OFF_LSW  (OFF_MW + 32)
#define OFF_C2W  (OFF_LSW + 32)
#define OFF_SC   (OFF_C2W + 16)
#define OFF_H    (((OFF_SC + 3) + 3) & ~3)
#define OFF_G    (OFF_H + H)
#define OFF_Z    (OFF_G + ROWS)
#define OFF_VH   (OFF_Z + 32)
#define OFF_SCAL (OFF_VH + 16)
#define SMEM_FLOATS (OFF_SCAL + 2)
#define SMEM_BYTES  (SMEM_FLOATS * 4)

static_assert(SMEM_BYTES <= 232448, "exceeds sm_100a dynamic smem cap");
static_assert((WPAD % 4) == 0 && (OFF_H % 4) == 0, "alignment");

__device__ __forceinline__ float fsig(float x) {
    return __fdividef(1.0f, 1.0f + __expf(-x));
}
__device__ __forceinline__ float ftanh(float x) {
    float ax = fabsf(x);
    float e  = __expf(-2.0f * ax);
    float t  = __fdividef(1.0f - e, 1.0f + e);
    return copysignf(t, x);
}
__device__ __forceinline__ float act3(float gi, float gg, float go) {
    float iv = fsig(gi);
    float gv = ftanh(gg);
    float ov = fsig(go);
    return ov * ftanh(iv * gv);
}
__device__ __forceinline__ void do_act(float* sm, int idx) {
    sm[OFF_H + idx] = act3(sm[OFF_G + idx], sm[OFF_G + 64 + idx], sm[OFF_G + 128 + idx]);
}

__device__ __forceinline__ void cp16(uint32_t dst_smem, const void* src) {
    asm volatile("cp.async.cg.shared.global [%0], [%1], 16;" :: "r"(dst_smem), "l"(src));
}
__device__ __forceinline__ void cp_commit() {
    asm volatile("cp.async.commit_group;");
}
template <int N>
__device__ __forceinline__ void cp_wait() {
    asm volatile("cp.async.wait_group %0;" :: "n"(N));
}

__global__ void __launch_bounds__(NT, 1)
net_kernel(const float* __restrict__ x, long long L,
           const float* __restrict__ Wih0,
           const float* __restrict__ bih0,
           const float* __restrict__ bhh0,
           const float* __restrict__ Wih,
           const float* __restrict__ bih,
           const float* __restrict__ bhh,
           const float* __restrict__ fc_w,
           const float* __restrict__ fc_b,
           const float* __restrict__ mean_w,
           const float* __restrict__ mean_b,
           const float* __restrict__ ls_w,
           const float* __restrict__ ls_b,
           const float* __restrict__ c1_w,
           const float* __restrict__ c1_b,
           const float* __restrict__ c2_w,
           const float* __restrict__ c2_b,
           float* __restrict__ out)
{
    extern __shared__ __align__(16) float sm[];
    const int tid = threadIdx.x;
    const uint32_t smbase = (uint32_t)__cvta_generic_to_shared(sm);

    #pragma unroll 1
    for (int rep = 0; rep < REPS; ++rep) {

        // ---- 1) stream big weights into padded rows, commit group/layer ----
        #pragma unroll
        for (int l = 0; l < 4; ++l) {
            for (int c = tid; c < ROWS * 16; c += NT) {
                int r = c >> 4, ch = c & 15;
                int grow = (r < 64) ? r : r + 64;
                uint32_t dst = smbase + (uint32_t)((OFF_W + (l * ROWS + r) * WPAD + ch * 4) * 4);
                cp16(dst, Wih + ((size_t)l * 256 + grow) * H + ch * 4);
            }
            cp_commit();
        }
        for (int c = tid; c < 32 * 16; c += NT) {
            int r = c >> 4, ch = c & 15;
            cp16(smbase + (uint32_t)((OFF_FC + r * WPAD + ch * 4) * 4), fc_w + r * H + ch * 4);
        }
        cp_commit();

        // ---- 2) stage small tensors ----
        const float xv = x[L - 1];
        if (tid < ROWS) {
            int grow = (tid < 64) ? tid : tid + 64;
            sm[OFF_W0 + tid] = Wih0[grow];
            sm[OFF_B0 + tid] = bih0[grow] + bhh0[grow];
        }
        for (int j = tid; j < 4 * ROWS; j += NT) {
            int l = j / ROWS, r = j - l * ROWS;
            int grow = (r < 64) ? r : r + 64;
            sm[OFF_BS + j] = bih[l * 256 + grow] + bhh[l * 256 + grow];
        }
        for (int j = tid; j < 512; j += NT) sm[OFF_C1W + j] = c1_w[j];
        if (tid < 32) {
            sm[OFF_FCB + tid] = fc_b[tid];
            sm[OFF_MW + tid]  = mean_w[tid];
            sm[OFF_LSW + tid] = ls_w[tid];
        }
        if (tid < 16) {
            sm[OFF_C1B + tid] = c1_b[tid];
            sm[OFF_C2W + tid] = c2_w[tid];
        }
        if (tid == 1) {
            sm[OFF_SC + 0] = mean_b[0];
            sm[OFF_SC + 1] = ls_b[0];
            sm[OFF_SC + 2] = c2_b[0];
        }
        __syncthreads();

        // ---- 3) layer 0 fused ----
        if (tid < H) {
            float gi = xv * sm[OFF_W0 + tid]       + sm[OFF_B0 + tid];
            float gg = xv * sm[OFF_W0 + 64 + tid]  + sm[OFF_B0 + 64 + tid];
            float go = xv * sm[OFF_W0 + 128 + tid] + sm[OFF_B0 + 128 + tid];
            sm[OFF_H + tid] = act3(gi, gg, go);
        }

        // ---- 4) layers 1..4 ----
        #pragma unroll
        for (int l = 0; l < 4; ++l) {
            switch (l) {
                case 0: cp_wait<4>(); break;
                case 1: cp_wait<3>(); break;
                case 2: cp_wait<2>(); break;
                case 3: cp_wait<1>(); break;
            }
            __syncthreads();
            if (tid < ROWS) {
                const float4* Wr = (const float4*)(sm + OFF_W + (l * ROWS + tid) * WPAD);
                const float4* hv = (const float4*)(sm + OFF_H);
                float a0 = 0.f, a1 = 0.f, a2 = 0.f, a3 = 0.f;
                #pragma unroll
                for (int j = 0; j < 16; j += 4) {
                    float4 w0 = Wr[j + 0], h0 = hv[j + 0];
                    float4 w1 = Wr[j + 1], h1 = hv[j + 1];
                    float4 w2 = Wr[j + 2], h2 = hv[j + 2];
                    float4 w3 = Wr[j + 3], h3 = hv[j + 3];
                    a0 += w0.x * h0.x + w0.y * h0.y + w0.z * h0.z + w0.w * h0.w;
                    a1 += w1.x * h1.x + w1.y * h1.y + w1.z * h1.z + w1.w * h1.w;
                    a2 += w2.x * h2.x + w2.y * h2.y + w2.z * h2.z + w2.w * h2.w;
                    a3 += w3.x * h3.x + w3.y * h3.y + w3.z * h3.z + w3.w * h3.w;
                }
                sm[OFF_G + tid] = (a0 + a1) + (a2 + a3) + sm[OFF_BS + l * ROWS + tid];
            }
            __syncthreads();
            if (tid < H) do_act(sm, tid);
        }

        cp_wait<0>();
        __syncthreads();

        // ---- 5) head ----
        if (tid < 32) {
            const float4* Wr = (const float4*)(sm + OFF_FC + tid * WPAD);
            const float4* hv = (const float4*)(sm + OFF_H);
            float a0 = 0.f, a1 = 0.f, a2 = 0.f, a3 = 0.f;
            #pragma unroll
            for (int j = 0; j < 16; j += 4) {
                float4 w0 = Wr[j + 0], h0 = hv[j + 0];
                float4 w1 = Wr[j + 1], h1 = hv[j + 1];
                float4 w2 = Wr[j + 2], h2 = hv[j + 2];
                float4 w3 = Wr[j + 3], h3 = hv[j + 3];
                a0 += w0.x * h0.x + w0.y * h0.y + w0.z * h0.z + w0.w * h0.w;
                a1 += w1.x * h1.x + w1.y * h1.y + w1.z * h1.z + w1.w * h1.w;
                a2 += w2.x * h2.x + w2.y * h2.y + w2.z * h2.z + w2.w * h2.w;
                a3 += w3.x * h3.x + w3.y * h3.y + w3.z * h3.z + w3.w * h3.w;
            }
            sm[OFF_Z + tid] = fmaxf((a0 + a1) + (a2 + a3) + sm[OFF_FCB + tid], 0.0f);
        }
        __syncthreads();

        // ---- 6) tiny heads ----
        if (tid < 16) {
            const float* Wr = sm + OFF_C1W + tid * 32;
            float a0 = 0.f, a1 = 0.f, a2 = 0.f, a3 = 0.f;
            #pragma unroll
            for (int k = 0; k < 32; k += 4) {
                int k0 = (k + 0 + 2 * tid) & 31;
                int k1 = (k + 1 + 2 * tid) & 31;
                int k2 = (k + 2 + 2 * tid) & 31;
                int k3 = (k + 3 + 2 * tid) & 31;
                a0 += sm[OFF_Z + k0] * Wr[k0];
                a1 += sm[OFF_Z + k1] * Wr[k1];
                a2 += sm[OFF_Z + k2] * Wr[k2];
                a3 += sm[OFF_Z + k3] * Wr[k3];
            }
            sm[OFF_VH + tid] = fmaxf((a0 + a1) + (a2 + a3) + sm[OFF_C1B + tid], 0.0f);
        } else if (tid == 16 || tid == 17) {
            const float* Wv = sm + ((tid == 16) ? OFF_MW : OFF_LSW);
            float a0 = 0.f, a1 = 0.f, a2 = 0.f, a3 = 0.f;
            #pragma unroll
            for (int k = 0; k < 32; k += 4) {
                a0 += sm[OFF_Z + k + 0] * Wv[k + 0];
                a1 += sm[OFF_Z + k + 1] * Wv[k + 1];
                a2 += sm[OFF_Z + k + 2] * Wv[k + 2];
                a3 += sm[OFF_Z + k + 3] * Wv[k + 3];
            }
            sm[OFF_SCAL + (tid - 16)] = (a0 + a1) + (a2 + a3) + sm[OFF_SC + (tid - 16)];
        }
        __syncthreads();

        if (tid == 0) {
            float a0 = 0.f, a1 = 0.f;
            #pragma unroll
            for (int k = 0; k < 16; k += 2) {
                a0 += sm[OFF_VH + k]     * sm[OFF_C2W + k];
                a1 += sm[OFF_VH + k + 1] * sm[OFF_C2W + k + 1];
            }
            out[0] = sm[OFF_SCAL + 0];
            out[1] = sm[OFF_SCAL + 1];
            out[2] = a0 + a1 + sm[OFF_SC + 2];
        }
        __syncthreads();   // iteration fully drained before next rep
    }
}

extern "C" void kernel_launch(void* const* d_in, const int* in_sizes, int n_in,
                              void* d_out, int out_size) {
    const float* x      = (const float*)d_in[0];
    const float* Wih0   = (const float*)d_in[1];
    const float* bih0   = (const float*)d_in[3];
    const float* bhh0   = (const float*)d_in[4];
    const float* Wih    = (const float*)d_in[5];
    const float* bih    = (const float*)d_in[7];
    const float* bhh    = (const float*)d_in[8];
    const float* fc_w   = (const float*)d_in[9];
    const float* fc_b   = (const float*)d_in[10];
    const float* mean_w = (const float*)d_in[11];
    const float* mean_b = (const float*)d_in[12];
    const float* ls_w   = (const float*)d_in[13];
    const float* ls_b   = (const float*)d_in[14];
    const float* c1_w   = (const float*)d_in[15];
    const float* c1_b   = (const float*)d_in[16];
    const float* c2_w   = (const float*)d_in[17];
    const float* c2_b   = (const float*)d_in[18];

    long long L = in_sizes[0];

    cudaFuncSetAttribute(net_kernel,
                         cudaFuncAttributeMaxDynamicSharedMemorySize, SMEM_BYTES);

    net_kernel<<<1, NT, SMEM_BYTES>>>(x, L, Wih0, bih0, bhh0, Wih, bih, bhh,
                                      fc_w, fc_b, mean_w, mean_b, ls_w, ls_b,
                                      c1_w, c1_b, c2_w, c2_b, (float*)d_out);
}

// round 15
// speedup vs baseline: 1.9154x; 1.9154x over previous
#include <cuda_runtime.h>
#include <cstdint>

// Net_60413009985719 — collapsed net (no recurrence, only x[L-1] matters,
// LSTM f-gate dead). R15 = R14 resubmitted (R14 died to broker infra, never
// ran). Instrumentation (R13) showed body=5.6us warm + 5.0us launch floor,
// L2 warm across graph replays => DELETE the SMEM weight pipeline; weights
// live in REGISTERS via direct LDG.128 from L2, prefetched one layer ahead.
// SMEM only carries h/G/z/vh (~1.3KB). NT=192, 6 warps.

#define H 64
#define NT 192

__device__ __forceinline__ float fsig(float x) {
    return __fdividef(1.0f, 1.0f + __expf(-x));
}
__device__ __forceinline__ float ftanh(float x) {
    float ax = fabsf(x);
    float e  = __expf(-2.0f * ax);            // in (0,1], no overflow
    float t  = __fdividef(1.0f - e, 1.0f + e);
    return copysignf(t, x);
}
__device__ __forceinline__ float act3(float gi, float gg, float go) {
    return fsig(go) * ftanh(fsig(gi) * ftanh(gg));
}

__global__ void __launch_bounds__(NT, 1)
net_kernel(const float* __restrict__ x, long long L,
           const float* __restrict__ Wih0,   // (256,1)
           const float* __restrict__ bih0,   // (256)
           const float* __restrict__ bhh0,   // (256)
           const float* __restrict__ Wih,    // (4,256,64)
           const float* __restrict__ bih,    // (4,256)
           const float* __restrict__ bhh,    // (4,256)
           const float* __restrict__ fc_w,   // (32,64)
           const float* __restrict__ fc_b,   // (32)
           const float* __restrict__ mean_w, // (32)
           const float* __restrict__ mean_b, // (1)
           const float* __restrict__ ls_w,   // (32)
           const float* __restrict__ ls_b,   // (1)
           const float* __restrict__ c1_w,   // (16,32)
           const float* __restrict__ c1_b,   // (16)
           const float* __restrict__ c2_w,   // (16)
           const float* __restrict__ c2_b,   // (1)
           float* __restrict__ out)
{
    __shared__ __align__(16) float shH[H];      // hidden vector
    __shared__ __align__(16) float shG[192];    // gate pre-activations (i,g,o)
    __shared__ __align__(16) float shZ[32];     // relu(fc)
    __shared__ __align__(16) float shVH[16];    // relu(c1)

    const int t = threadIdx.x;                  // 0..191
    const float xv = x[L - 1];                  // issue first: overlaps prefetch
    // live gmem gate row for this thread: i:[0,64) g:[128,192) o:[192,256)
    const int grow = (t < 64) ? t : t + 64;

    // ---- prefetch layer-1 W row into registers (deepest-latency first) ----
    float4 wreg[16];
    {
        const float4* gW = (const float4*)(Wih + (size_t)grow * H);
        #pragma unroll
        for (int j = 0; j < 16; ++j) wreg[j] = gW[j];
    }
    // per-layer biases for my row (layers 1..4)
    float br[4];
    #pragma unroll
    for (int l = 0; l < 4; ++l)
        br[l] = bih[l * 256 + grow] + bhh[l * 256 + grow];
    // role-specific head scalars
    float fcb = (t < 32) ? fc_b[t] : 0.0f;
    float c1b = (t >= 32 && t < 48) ? c1_b[t - 32] : 0.0f;
    float tailb = 0.0f;
    if (t == 48) tailb = mean_b[0];
    else if (t == 49) tailb = ls_b[0];
    else if (t == 50) tailb = c2_b[0];

    // ---- layer 0: each act thread computes its own 3 gates from scalar ----
    if (t < 64) {
        float gi = xv * Wih0[t]       + bih0[t]       + bhh0[t];
        float gg = xv * Wih0[t + 128] + bih0[t + 128] + bhh0[t + 128];
        float go = xv * Wih0[t + 192] + bih0[t + 192] + bhh0[t + 192];
        shH[t] = act3(gi, gg, go);
    }
    __syncthreads();

    // ---- layers 1..4: register-resident W, broadcast h from SMEM ----
    #pragma unroll
    for (int l = 0; l < 4; ++l) {
        const float4* hv = (const float4*)shH;
        float a0 = 0.f, a1 = 0.f, a2 = 0.f, a3 = 0.f;
        #pragma unroll
        for (int j = 0; j < 16; j += 4) {
            float4 h0 = hv[j + 0], h1 = hv[j + 1], h2 = hv[j + 2], h3 = hv[j + 3];
            a0 += wreg[j + 0].x * h0.x + wreg[j + 0].y * h0.y
                + wreg[j + 0].z * h0.z + wreg[j + 0].w * h0.w;
            a1 += wreg[j + 1].x * h1.x + wreg[j + 1].y * h1.y
                + wreg[j + 1].z * h1.z + wreg[j + 1].w * h1.w;
            a2 += wreg[j + 2].x * h2.x + wreg[j + 2].y * h2.y
                + wreg[j + 2].z * h2.z + wreg[j + 2].w * h2.w;
            a3 += wreg[j + 3].x * h3.x + wreg[j + 3].y * h3.y
                + wreg[j + 3].z * h3.z + wreg[j + 3].w * h3.w;
        }
        shG[t] = (a0 + a1) + (a2 + a3) + br[l];

        // prefetch the NEXT weights into wreg (after last use of current)
        if (l < 3) {
            const float4* gW = (const float4*)(Wih + ((size_t)(l + 1) * 256 + grow) * H);
            #pragma unroll
            for (int j = 0; j < 16; ++j) wreg[j] = gW[j];
        } else {
            // last layer: prefetch head weights into the same buffer
            if (t < 32) {
                const float4* gW = (const float4*)(fc_w + t * H);
                #pragma unroll
                for (int j = 0; j < 16; ++j) wreg[j] = gW[j];
            } else if (t < 48) {
                const float4* gW = (const float4*)(c1_w + (t - 32) * 32);
                #pragma unroll
                for (int j = 0; j < 8; ++j) wreg[j] = gW[j];
            } else if (t == 48) {
                const float4* gW = (const float4*)mean_w;
                #pragma unroll
                for (int j = 0; j < 8; ++j) wreg[j] = gW[j];
            } else if (t == 49) {
                const float4* gW = (const float4*)ls_w;
                #pragma unroll
                for (int j = 0; j < 8; ++j) wreg[j] = gW[j];
            } else if (t == 50) {
                const float4* gW = (const float4*)c2_w;
                #pragma unroll
                for (int j = 0; j < 4; ++j) wreg[j] = gW[j];
            }
        }
        __syncthreads();
        if (t < 64)
            shH[t] = act3(shG[t], shG[t + 64], shG[t + 128]);
        __syncthreads();
    }

    // ---- head: z = relu(fc_w @ h + fc_b), weights already in regs ----
    if (t < 32) {
        const float4* hv = (const float4*)shH;
        float a0 = 0.f, a1 = 0.f, a2 = 0.f, a3 = 0.f;
        #pragma unroll
        for (int j = 0; j < 16; j += 4) {
            float4 h0 = hv[j + 0], h1 = hv[j + 1], h2 = hv[j + 2], h3 = hv[j + 3];
            a0 += wreg[j + 0].x * h0.x + wreg[j + 0].y * h0.y
                + wreg[j + 0].z * h0.z + wreg[j + 0].w * h0.w;
            a1 += wreg[j + 1].x * h1.x + wreg[j + 1].y * h1.y
                + wreg[j + 1].z * h1.z + wreg[j + 1].w * h1.w;
            a2 += wreg[j + 2].x * h2.x + wreg[j + 2].y * h2.y
                + wreg[j + 2].z * h2.z + wreg[j + 2].w * h2.w;
            a3 += wreg[j + 3].x * h3.x + wreg[j + 3].y * h3.y
                + wreg[j + 3].z * h3.z + wreg[j + 3].w * h3.w;
        }
        shZ[t] = fmaxf((a0 + a1) + (a2 + a3) + fcb, 0.0f);
    }
    __syncthreads();

    // ---- tiny heads: c1 (t=32..47), mean (t=48), log_std (t=49) ----
    if (t >= 32 && t < 48) {
        const float4* zv = (const float4*)shZ;
        float a0 = 0.f, a1 = 0.f;
        #pragma unroll
        for (int j = 0; j < 8; j += 2) {
            float4 z0 = zv[j + 0], z1 = zv[j + 1];
            a0 += wreg[j + 0].x * z0.x + wreg[j + 0].y * z0.y
                + wreg[j + 0].z * z0.z + wreg[j + 0].w * z0.w;
            a1 += wreg[j + 1].x * z1.x + wreg[j + 1].y * z1.y
                + wreg[j + 1].z * z1.z + wreg[j + 1].w * z1.w;
        }
        shVH[t - 32] = fmaxf(a0 + a1 + c1b, 0.0f);
    } else if (t == 48 || t == 49) {
        const float4* zv = (const float4*)shZ;
        float a0 = 0.f, a1 = 0.f;
        #pragma unroll
        for (int j = 0; j < 8; j += 2) {
            float4 z0 = zv[j + 0], z1 = zv[j + 1];
            a0 += wreg[j + 0].x * z0.x + wreg[j + 0].y * z0.y
                + wreg[j + 0].z * z0.z + wreg[j + 0].w * z0.w;
            a1 += wreg[j + 1].x * z1.x + wreg[j + 1].y * z1.y
                + wreg[j + 1].z * z1.z + wreg[j + 1].w * z1.w;
        }
        out[t - 48] = a0 + a1 + tailb;     // out[0]=mean, out[1]=log_std
    }
    __syncthreads();

    // ---- value head: t=50 holds c2_w in regs ----
    if (t == 50) {
        const float4* vv = (const float4*)shVH;
        float a0 = 0.f, a1 = 0.f;
        #pragma unroll
        for (int j = 0; j < 4; j += 2) {
            float4 v0 = vv[j + 0], v1 = vv[j + 1];
            a0 += wreg[j + 0].x * v0.x + wreg[j + 0].y * v0.y
                + wreg[j + 0].z * v0.z + wreg[j + 0].w * v0.w;
            a1 += wreg[j + 1].x * v1.x + wreg[j + 1].y * v1.y
                + wreg[j + 1].z * v1.z + wreg[j + 1].w * v1.w;
        }
        out[2] = a0 + a1 + tailb;
    }
}

extern "C" void kernel_launch(void* const* d_in, const int* in_sizes, int n_in,
                              void* d_out, int out_size) {
    const float* x      = (const float*)d_in[0];
    const float* Wih0   = (const float*)d_in[1];
    const float* bih0   = (const float*)d_in[3];
    const float* bhh0   = (const float*)d_in[4];
    const float* Wih    = (const float*)d_in[5];
    const float* bih    = (const float*)d_in[7];
    const float* bhh    = (const float*)d_in[8];
    const float* fc_w   = (const float*)d_in[9];
    const float* fc_b   = (const float*)d_in[10];
    const float* mean_w = (const float*)d_in[11];
    const float* mean_b = (const float*)d_in[12];
    const float* ls_w   = (const float*)d_in[13];
    const float* ls_b   = (const float*)d_in[14];
    const float* c1_w   = (const float*)d_in[15];
    const float* c1_b   = (const float*)d_in[16];
    const float* c2_w   = (const float*)d_in[17];
    const float* c2_b   = (const float*)d_in[18];

    long long L = in_sizes[0];

    net_kernel<<<1, NT>>>(x, L, Wih0, bih0, bhh0, Wih, bih, bhh,
                          fc_w, fc_b, mean_w, mean_b, ls_w, ls_b,
                          c1_w, c1_b, c2_w, c2_b, (float*)d_out);
}

// round 16
// speedup vs baseline: 1.9196x; 1.0022x over previous
#include <cuda_runtime.h>
#include <cstdint>

// Net_60413009985719 — collapsed net (no recurrence, only x[L-1] matters,
// LSTM f-gate dead). R16 = R15's register-resident design with the spill
// fixed: NT=384, TWO threads per row, wreg[8] (32 regs) instead of wreg[16]
// (64 regs). R15 hit regs=255 + local-memory spills; halving the footprint
// keeps prefetch overlap within budget. Partner combine via shfl_xor(1).

#define H 64
#define NT 384

__device__ __forceinline__ float fsig(float x) {
    return __fdividef(1.0f, 1.0f + __expf(-x));
}
__device__ __forceinline__ float ftanh(float x) {
    float ax = fabsf(x);
    float e  = __expf(-2.0f * ax);            // in (0,1], no overflow
    float t  = __fdividef(1.0f - e, 1.0f + e);
    return copysignf(t, x);
}
__device__ __forceinline__ float act3(float gi, float gg, float go) {
    return fsig(go) * ftanh(fsig(gi) * ftanh(gg));
}

__device__ __forceinline__ float dot8(const float4* __restrict__ w,
                                      const float4* __restrict__ v) {
    float a0 = 0.f, a1 = 0.f, a2 = 0.f, a3 = 0.f;
    #pragma unroll
    for (int j = 0; j < 8; j += 4) {
        float4 v0 = v[j + 0], v1 = v[j + 1], v2 = v[j + 2], v3 = v[j + 3];
        a0 += w[j + 0].x * v0.x + w[j + 0].y * v0.y + w[j + 0].z * v0.z + w[j + 0].w * v0.w;
        a1 += w[j + 1].x * v1.x + w[j + 1].y * v1.y + w[j + 1].z * v1.z + w[j + 1].w * v1.w;
        a2 += w[j + 2].x * v2.x + w[j + 2].y * v2.y + w[j + 2].z * v2.z + w[j + 2].w * v2.w;
        a3 += w[j + 3].x * v3.x + w[j + 3].y * v3.y + w[j + 3].z * v3.z + w[j + 3].w * v3.w;
    }
    return (a0 + a1) + (a2 + a3);
}
__device__ __forceinline__ float dot4(const float4* __restrict__ w,
                                      const float4* __restrict__ v) {
    float a0 = 0.f, a1 = 0.f;
    #pragma unroll
    for (int j = 0; j < 4; j += 2) {
        float4 v0 = v[j + 0], v1 = v[j + 1];
        a0 += w[j + 0].x * v0.x + w[j + 0].y * v0.y + w[j + 0].z * v0.z + w[j + 0].w * v0.w;
        a1 += w[j + 1].x * v1.x + w[j + 1].y * v1.y + w[j + 1].z * v1.z + w[j + 1].w * v1.w;
    }
    return a0 + a1;
}

__global__ void __launch_bounds__(NT, 1)
net_kernel(const float* __restrict__ x, long long L,
           const float* __restrict__ Wih0,   // (256,1)
           const float* __restrict__ bih0,   // (256)
           const float* __restrict__ bhh0,   // (256)
           const float* __restrict__ Wih,    // (4,256,64)
           const float* __restrict__ bih,    // (4,256)
           const float* __restrict__ bhh,    // (4,256)
           const float* __restrict__ fc_w,   // (32,64)
           const float* __restrict__ fc_b,   // (32)
           const float* __restrict__ mean_w, // (32)
           const float* __restrict__ mean_b, // (1)
           const float* __restrict__ ls_w,   // (32)
           const float* __restrict__ ls_b,   // (1)
           const float* __restrict__ c1_w,   // (16,32)
           const float* __restrict__ c1_b,   // (16)
           const float* __restrict__ c2_w,   // (16)
           const float* __restrict__ c2_b,   // (1)
           float* __restrict__ out)
{
    __shared__ __align__(16) float shH[H];      // hidden vector
    __shared__ __align__(16) float shG[192];    // gate pre-activations (i,g,o)
    __shared__ __align__(16) float shZ[32];     // relu(fc)
    __shared__ __align__(16) float shVH[16];    // relu(c1)

    const int t = threadIdx.x;                  // 0..383
    const float xv = x[L - 1];                  // issue first: overlaps prefetch
    const int row  = t >> 1;                    // 0..191
    const int half = t & 1;                     // which 32-float half of the row
    // live gmem gate row: i:[0,64) g:[128,192) o:[192,256)
    const int grow = (row < 64) ? row : row + 64;

    // ---- prefetch layer-1 half-row into registers ----
    float4 wreg[8];
    {
        const float4* gW = (const float4*)(Wih + (size_t)grow * H + half * 32);
        #pragma unroll
        for (int j = 0; j < 8; ++j) wreg[j] = gW[j];
    }
    // per-layer bias for my row (only the half-0 writer needs it)
    float br[4];
    #pragma unroll
    for (int l = 0; l < 4; ++l)
        br[l] = bih[l * 256 + grow] + bhh[l * 256 + grow];
    // role-specific head scalars
    float fcb = (t < 64 && half == 0) ? fc_b[row] : 0.0f;
    float c1b = (t >= 64 && t < 96 && half == 0) ? c1_b[(t - 64) >> 1] : 0.0f;
    float tailb = 0.0f;
    if (t == 96) tailb = mean_b[0];
    else if (t == 98) tailb = ls_b[0];
    else if (t == 100) tailb = c2_b[0];

    // ---- layer 0: act threads compute their own gates from scalar ----
    if (t < 64) {
        float gi = xv * Wih0[t]       + bih0[t]       + bhh0[t];
        float gg = xv * Wih0[t + 128] + bih0[t + 128] + bhh0[t + 128];
        float go = xv * Wih0[t + 192] + bih0[t + 192] + bhh0[t + 192];
        shH[t] = act3(gi, gg, go);
    }
    __syncthreads();

    // ---- layers 1..4: register W (half-row), shfl-combined ----
    #pragma unroll
    for (int l = 0; l < 4; ++l) {
        const float4* hv = (const float4*)shH + half * 8;
        float acc = dot8(wreg, hv);
        acc += __shfl_xor_sync(0xFFFFFFFFu, acc, 1);
        if (half == 0) shG[row] = acc + br[l];

        // prefetch NEXT half-row weights (after last use of current wreg)
        if (l < 3) {
            const float4* gW = (const float4*)(Wih + ((size_t)(l + 1) * 256 + grow) * H + half * 32);
            #pragma unroll
            for (int j = 0; j < 8; ++j) wreg[j] = gW[j];
        } else {
            // last layer: head weights into the same buffer, split by role
            if (t < 64) {                       // fc: 2 threads per row
                const float4* gW = (const float4*)(fc_w + row * H + half * 32);
                #pragma unroll
                for (int j = 0; j < 8; ++j) wreg[j] = gW[j];
            } else if (t < 96) {                // c1: 2 threads per row (16 fl each)
                const float4* gW = (const float4*)(c1_w + ((t - 64) >> 1) * 32 + half * 16);
                #pragma unroll
                for (int j = 0; j < 4; ++j) wreg[j] = gW[j];
            } else if (t < 100) {               // mean (96,97) / ls (98,99) halves
                const float* base = (t < 98) ? mean_w : ls_w;
                const float4* gW = (const float4*)(base + half * 16);
                #pragma unroll
                for (int j = 0; j < 4; ++j) wreg[j] = gW[j];
            } else if (t == 100) {              // c2: one thread, 16 floats
                const float4* gW = (const float4*)c2_w;
                #pragma unroll
                for (int j = 0; j < 4; ++j) wreg[j] = gW[j];
            }
        }
        __syncthreads();
        if (t < 64)
            shH[t] = act3(shG[t], shG[t + 64], shG[t + 128]);
        __syncthreads();
    }

    // ---- head: z = relu(fc_w @ h + fc_b), 2 threads per row ----
    if (t < 64) {
        const float4* hv = (const float4*)shH + half * 8;
        float acc = dot8(wreg, hv);
        acc += __shfl_xor_sync(0xFFFFFFFFu, acc, 1);
        if (half == 0) shZ[row] = fmaxf(acc + fcb, 0.0f);
    }
    __syncthreads();

    // ---- tiny heads ----
    if (t >= 64 && t < 96) {                    // c1: rows 0..15, 2 threads each
        const float4* zv = (const float4*)shZ + half * 4;
        float acc = dot4(wreg, zv);
        acc += __shfl_xor_sync(0xFFFFFFFFu, acc, 1);
        if (half == 0) shVH[(t - 64) >> 1] = fmaxf(acc + c1b, 0.0f);
    } else if (t >= 96 && t < 100) {            // mean (96,97) / ls (98,99)
        const float4* zv = (const float4*)shZ + half * 4;
        float acc = dot4(wreg, zv);
        acc += __shfl_xor_sync(0xFu, acc, 1);   // lanes 0..3 of warp 3
        if (t == 96) out[0] = acc + tailb;
        else if (t == 98) out[1] = acc + tailb;
    }
    __syncthreads();

    if (t == 100) {                             // value head
        out[2] = dot4(wreg, (const float4*)shVH) + tailb;
    }
}

extern "C" void kernel_launch(void* const* d_in, const int* in_sizes, int n_in,
                              void* d_out, int out_size) {
    const float* x      = (const float*)d_in[0];
    const float* Wih0   = (const float*)d_in[1];
    const float* bih0   = (const float*)d_in[3];
    const float* bhh0   = (const float*)d_in[4];
    const float* Wih    = (const float*)d_in[5];
    const float* bih    = (const float*)d_in[7];
    const float* bhh    = (const float*)d_in[8];
    const float* fc_w   = (const float*)d_in[9];
    const float* fc_b   = (const float*)d_in[10];
    const float* mean_w = (const float*)d_in[11];
    const float* mean_b = (const float*)d_in[12];
    const float* ls_w   = (const float*)d_in[13];
    const float* ls_b   = (const float*)d_in[14];
    const float* c1_w   = (const float*)d_in[15];
    const float* c1_b   = (const float*)d_in[16];
    const float* c2_w   = (const float*)d_in[17];
    const float* c2_b   = (const float*)d_in[18];

    long long L = in_sizes[0];

    net_kernel<<<1, NT>>>(x, L, Wih0, bih0, bhh0, Wih, bih, bhh,
                          fc_w, fc_b, mean_w, mean_b, ls_w, ls_b,
                          c1_w, c1_b, c2_w, c2_b, (float*)d_out);
}